// round 9
// baseline (speedup 1.0000x reference)
#include <cuda_runtime.h>
#include <cstdint>
#include <math.h>

#define BATCH 4096
#define INF   128
#define OUTF  128
#define POST_STRIDE (OUTF * INF)      // 16384 floats per batch row of postacts
#define Y_ELEMS (BATCH * OUTF)        // 524288

// x_red stored TILE-TRANSPOSED for kan's access pattern:
// g_xredT4[i4][b] = float4( x_red[b][4*i4 .. 4*i4+3] ),  i4 in [0,32), b in [0,4096).
// 2 MB static device scratch (no dynamic allocation).
__device__ float4 g_xredT4[INF / 4][BATCH];

// ---------------------------------------------------------------------------
// Kernel 1: x_red[b, j] = sum_i x[b, i] * mask[j, i], written transposed.
// 256 blocks (16 b-rows each) x 128 threads (thread = one j). One sync.
// Fat b-tile amortizes the 64 KB mask stream (16 MB total L2 traffic).
// ---------------------------------------------------------------------------
__global__ __launch_bounds__(128) void xred_kernel(const float* __restrict__ x,
                                                   const float* __restrict__ mask) {
    __shared__ float4 sx4[16][32];         // 16 b-rows x 128 floats

    const int tid = threadIdx.x;           // j
    const int b0  = blockIdx.x * 16;

    const float4* x4 = reinterpret_cast<const float4*>(x) + (size_t)b0 * 32;
#pragma unroll
    for (int k = 0; k < 4; ++k) {
        int idx = tid + k * 128;           // 0..511
        sx4[idx >> 5][idx & 31] = x4[idx];
    }
    __syncthreads();

    const float4* m4 = reinterpret_cast<const float4*>(mask) + (size_t)tid * 32;

    float acc[16];
#pragma unroll
    for (int b = 0; b < 16; ++b) acc[b] = 0.0f;

#pragma unroll 4
    for (int q = 0; q < 32; ++q) {
        float4 mv = __ldg(&m4[q]);
#pragma unroll
        for (int b = 0; b < 16; ++b) {
            float4 xv = sx4[b][q];         // broadcast: conflict-free
            acc[b] += mv.x * xv.x + mv.y * xv.y + mv.z * xv.z + mv.w * xv.w;
        }
    }

    const int i4   = tid >> 2;             // which float4 group of i
    const int comp = tid & 3;              // component within the float4
#pragma unroll
    for (int b = 0; b < 16; ++b)
        reinterpret_cast<float*>(&g_xredT4[i4][b0 + b])[comp] = acc[b];
}

// ---------------------------------------------------------------------------
// Activation body. `id` is warp-uniform at every call site -> single branch
// taken per warp. MUFU-based fast paths (abs err ~1e-6), atanf stays libm.
// ---------------------------------------------------------------------------
__device__ __forceinline__ float apply_fn(int id, float z) {
    switch (id) {
        case 0: return z;
        case 1: return z * z;
        case 2: return z * z * z;
        case 3: return __sinf(z);
        case 4: {                                   // tanh, saturates correctly at +/-inf
            float e = __expf(2.0f * z);
            return 1.0f - 2.0f * __fdividef(1.0f, e + 1.0f);
        }
        case 5: return __fdividef(1.0f, 1.0f + __expf(-z));   // sigmoid
        case 6: return __expf(-z * z);
        case 7: return fabsf(z);
        case 8: return atanf(z);
        default: return __expf(z);                  // id == 9
    }
}

// ---------------------------------------------------------------------------
// Kernel 2: main KAN layer.
// Grid: (r = 128, b_tile = 128), 256 threads (8 warps).
// Warp w owns i in [w*16, w*16+16); lanes map to the 32 batch rows of the
// tile -> fun_id is UNIFORM per warp-iteration (no divergence).
// x_red arrives via coalesced LDG.128 from pre-transposed g_xredT4.
// postacts tile staged in so[] (stride 132: conflict-free STS), then shipped
// with per-row cp.async.bulk (UBLKCP) smem->gmem copies: no epilogue LDS/STG,
// the async engine streams 512B rows to their strided destinations.
// ---------------------------------------------------------------------------
__global__ __launch_bounds__(256) void kan_kernel(const float4* __restrict__ affine4,
                                                  const int*   __restrict__ fids,
                                                  float*       __restrict__ out) {
    const int r  = blockIdx.x;
    const int b0 = blockIdx.y << 5;        // 32-batch tile

    __shared__ __align__(16) float so[32][132];
    __shared__ float4 saf[128];            // affine[r][i][0..3]
    __shared__ int4   sf4[32];             // fun_ids packed 4-wide
    __shared__ float  spart[8][32];

    const int tid = threadIdx.x;

    if (tid < 128) {
        saf[tid] = affine4[r * 128 + tid];
    } else if (tid < 160) {
        sf4[tid - 128] = reinterpret_cast<const int4*>(fids)[r * 32 + (tid - 128)];
    }
    __syncthreads();

    const int lane = tid & 31;
    const int w    = tid >> 5;
    const int i4w  = w << 2;               // first i4 group of this warp

    // Front-batched, fully coalesced x loads (lanes = consecutive b).
    float4 xv[4];
#pragma unroll
    for (int g = 0; g < 4; ++g)
        xv[g] = g_xredT4[i4w + g][b0 + lane];

    float acc = 0.0f;
#pragma unroll
    for (int g = 0; g < 4; ++g) {
        const int  i4  = i4w + g;
        const int  i0  = i4 << 2;
        const int4 id4 = sf4[i4];          // 1 LDS.128 broadcast
        float4 pv;
        {
            float4 af = saf[i0 + 0];       // LDS.128 broadcast
            pv.x = fmaf(af.z, apply_fn(id4.x, fmaf(af.x, xv[g].x, af.y)), af.w);
        }
        {
            float4 af = saf[i0 + 1];
            pv.y = fmaf(af.z, apply_fn(id4.y, fmaf(af.x, xv[g].y, af.y)), af.w);
        }
        {
            float4 af = saf[i0 + 2];
            pv.z = fmaf(af.z, apply_fn(id4.z, fmaf(af.x, xv[g].z, af.y)), af.w);
        }
        {
            float4 af = saf[i0 + 3];
            pv.w = fmaf(af.z, apply_fn(id4.w, fmaf(af.x, xv[g].w, af.y)), af.w);
        }
        *reinterpret_cast<float4*>(&so[lane][i0]) = pv;    // STS.128, conflict-free
        acc += (pv.x + pv.y) + (pv.z + pv.w);
    }
    spart[w][lane] = acc;
    __syncthreads();

    // Make generic-proxy STS writes visible to the async proxy, then ship
    // each 512B row with one bulk copy (destination stride 64KB is irrelevant
    // to per-row copies). y reduction overlaps the in-flight copies.
    asm volatile("fence.proxy.async.shared::cta;" ::: "memory");
    if (tid < 32) {
        const int b = tid;
        unsigned int src = (unsigned int)__cvta_generic_to_shared(&so[b][0]);
        float* dst = out + Y_ELEMS + (size_t)(b0 + b) * POST_STRIDE + (size_t)r * INF;
        asm volatile("cp.async.bulk.global.shared::cta.bulk_group [%0], [%1], %2;"
                     :: "l"(dst), "r"(src), "r"(512u) : "memory");
        asm volatile("cp.async.bulk.commit_group;" ::: "memory");

        // y[b, r] = sum_i postacts[b, r, i]
        float s = spart[0][b];
#pragma unroll
        for (int ww = 1; ww < 8; ++ww) s += spart[ww][b];
        out[(size_t)(b0 + b) * OUTF + r] = s;

        asm volatile("cp.async.bulk.wait_group 0;" ::: "memory");
    }
}

// ---------------------------------------------------------------------------
extern "C" void kernel_launch(void* const* d_in, const int* in_sizes, int n_in,
                              void* d_out, int out_size) {
    const float*  x      = (const float*)d_in[0];
    const float4* affine = (const float4*)d_in[1];
    const float*  mask   = (const float*)d_in[2];
    const int*    fid    = (const int*)d_in[3];
    float*        out    = (float*)d_out;

    (void)in_sizes; (void)n_in; (void)out_size;

    xred_kernel<<<BATCH / 16, 128>>>(x, mask);
    kan_kernel<<<dim3(OUTF, BATCH / 32), 256>>>(affine, fid, out);
}